// round 15
// baseline (speedup 1.0000x reference)
#include <cuda_runtime.h>
#include <cuda_bf16.h>
#include <cstdint>

// ---------------- problem constants ----------------
#define BATCH   16
#define TT      8192
#define NPRE    128
#define NPOST   128
#define CHUNK   1024              // timesteps per CTA
#define SC      64                // sub-chunk (MMA K tile / pipeline block)
#define NBLK    (CHUNK / SC)      // 16
#define NCTA    (BATCH * TT / CHUNK)  // 128
#define LWIN    60                // filter length (taps 1..59)

#define TAU_F       20.0f
#define A_PLUS_F    0.005f
#define A_MINUS_F   0.00525f
#define TARGET_RATE 0.1f
#define HOM_RATE    0.001f
#define TAU_HOM     1000.0f

// ---------------- smem layout (224 KB, 1 CTA/SM) ----------------
#define POST_SLOT_BYTES (SC * 128 * 4)        // 32768; 5-slot ring (depth-3 cp.async)
#define NSLOT           5
#define TILE_BYTES      (128 * 64 * 2)        // 16384: [128 rows][64 bf16], XOR-swizzled
#define SET_BYTES       (2 * TILE_BYTES)      // preT + hT
#define OFF_TILES       (NSLOT * POST_SLOT_BYTES)      // 163840
#define SMEM_BYTES      (OFF_TILES + 2 * SET_BYTES)    // 229376 (224 KB)

// ---------------- scratch (static device, no allocs) ----------------
__device__ float g_partials[(size_t)NCTA * NPRE * NPOST];   // 8 MB
__device__ float g_part2[8 * NPRE * NPOST];                 // 512 KB
__device__ float g_colsum_part[NCTA * NPOST];               // 64 KB
__device__ float g_errq[NPOST];

__device__ __forceinline__ float decode_dt(const void* p) {
    if (p == nullptr) return 1.0f;
    int iv = *(const int*)p;
    if (iv >= 1 && iv <= 1000000) return (float)iv;   // int32/int64 low word
    return *(const float*)p;                          // float32 bits
}
__device__ __forceinline__ unsigned smem_u32(const void* p) {
    return (unsigned)__cvta_generic_to_shared(p);
}

// ==========================================================================
// Kernel 1: software-pipelined filter/transpose + bf16 HMMA, depth-3 cp.async
// grid = 128 CTAs (one (b, 1024-t) unit each), 256 threads
// ==========================================================================
__global__ __launch_bounds__(256)
void stdp_main(const float* __restrict__ pre, const float* __restrict__ post,
               const void* __restrict__ dtp)
{
    extern __shared__ char smem[];
    char* post_base = smem;                       // 5 slots [64 t][128 q] fp32

    const int tid  = threadIdx.x;
    const int lane = tid & 31;
    const int w    = tid >> 5;
    const int u    = blockIdx.x;
    const int b    = u >> 3;               // 8 units per batch
    const int t0   = (u & 7) * CHUNK;

    const float dt  = decode_dt(dtp);
    const float r   = expf(-dt / TAU_F);
    const float g0  = A_PLUS_F - A_MINUS_F;          // TAU_PLUS == TAU_MINUS
    const float c1  = r * g0;
    const float c60 = g0 * expf(-60.0f * dt / TAU_F);

    const char*  postg = (const char*)(post + (size_t)b * TT * 128);
    const float* preg  = pre + (size_t)b * TT * 128;

    // stage post block k -> ring slot k%5 (zero-fill past T), one commit group
    auto load_post = [&](int k) {
        const int tb0  = t0 + k * SC;
        const int slot = k % NSLOT;
        #pragma unroll
        for (int i = tid; i < SC * 32; i += 256) {            // 2048 x 16B
            const int rr = i >> 5, c4 = i & 31;
            const int t  = tb0 + rr;
            const unsigned dst = smem_u32(post_base + slot * POST_SLOT_BYTES
                                          + rr * 512 + c4 * 16);
            const char* src = postg + ((size_t)(t < TT ? t : 0) * 512 + c4 * 16);
            const int ss = (t < TT) ? 16 : 0;
            asm volatile("cp.async.cg.shared.global [%0], [%1], 16, %2;\n"
                         :: "r"(dst), "l"(src), "r"(ss));
        }
        asm volatile("cp.async.commit_group;\n");
    };

    // pre block j -> registers (transpose warps only), {0,1} -> bf16 via PRMT (exact)
    unsigned regs[8][4];
    auto ldg_pre = [&](int j) {
        const int wi = w - 4;
        const float* pg = preg + (size_t)(t0 + j * SC) * 128;
        #pragma unroll
        for (int it = 0; it < 8; ++it) {
            const int tile = wi * 8 + it;
            const int tb = tile & 7;      // t block of 8
            const int pb = tile >> 3;     // p block of 32
            const int trow = tb * 8 + (lane >> 2);
            const int pc   = pb * 32 + 2 * (lane & 3);
            #pragma unroll
            for (int j2 = 0; j2 < 4; ++j2) {
                const float2 v = *(const float2*)(pg + (size_t)trow * 128 + pc + 8 * j2);
                regs[it][j2] = __byte_perm(__float_as_uint(v.x),
                                           __float_as_uint(v.y), 0x7632);
            }
        }
    };

    float hcarry = 0.0f;   // filter state (tid<128, one q each)
    float colsum = 0.0f;

    // produce tiles for block j into set j&1
    auto produce = [&](int j, bool init_carry) {
        char* preT_s = smem + OFF_TILES + (j & 1) * SET_BYTES;
        char* hT_s   = preT_s + TILE_BYTES;
        const float* cur = (const float*)(post_base + (j % NSLOT) * POST_SLOT_BYTES);
        const float* nxt = (const float*)(post_base + ((j + 1) % NSLOT) * POST_SLOT_BYTES);

        if (tid < 128) {
            // ---------- h filter (exact backward recurrence) -> hT bf16 ----------
            const int q = tid;
            if (init_carry) {
                float hh = 0.0f, wc = g0;
                #pragma unroll 4
                for (int tau = 1; tau < LWIN; ++tau) {
                    wc *= r;
                    hh += wc * nxt[(tau - 1) * 128 + q];
                }
                hcarry = hh;
            }
            #pragma unroll
            for (int g8 = SC / 8 - 1; g8 >= 0; --g8) {
                unsigned hp0 = 0, hp1 = 0, hp2 = 0, hp3 = 0, stash = 0;
                #pragma unroll
                for (int e = 7; e >= 0; --e) {
                    const int lt = g8 * 8 + e;
                    const unsigned uh =
                        (unsigned)__bfloat16_as_ushort(__float2bfloat16_rn(hcarry));
                    if (e & 1) stash = uh << 16;
                    else {
                        const unsigned wv = stash | uh;
                        if (e == 0) hp0 = wv; else if (e == 2) hp1 = wv;
                        else if (e == 4) hp2 = wv; else hp3 = wv;
                    }
                    const float s1  = cur[lt * 128 + q];
                    const float s60 = (lt < 5) ? cur[(lt + 59) * 128 + q]
                                               : nxt[(lt - 5) * 128 + q];
                    colsum += s1;        // exact integer column count
                    hcarry = fmaf(r, hcarry, fmaf(c1, s1, -c60 * s60));
                }
                const unsigned off = q * 128 + ((g8 << 4) ^ ((q & 7) << 4));
                uint4 v; v.x = hp0; v.y = hp1; v.z = hp2; v.w = hp3;
                *(uint4*)(hT_s + off) = v;   // conflict-free STS.128
            }
        } else {
            // ---------- stmatrix regs -> preT[p][t] (swizzled packed) ----------
            const int wi = w - 4;
            #pragma unroll
            for (int it = 0; it < 8; ++it) {
                const int tile = wi * 8 + it;
                const int tb = tile & 7;
                const int pb = tile >> 3;
                const int row = pb * 32 + (lane >> 3) * 8 + (lane & 7);
                const unsigned daddr = smem_u32(
                    preT_s + row * 128 + (((unsigned)tb << 4) ^ (((unsigned)row & 7) << 4)));
                asm volatile(
                    "stmatrix.sync.aligned.m8n8.x4.trans.shared.b16 [%0], {%1,%2,%3,%4};\n"
                    :: "r"(daddr), "r"(regs[it][0]), "r"(regs[it][1]),
                       "r"(regs[it][2]), "r"(regs[it][3]));
            }
        }
    };

    // MMA accumulators: warp w -> p in [ (w&3)*32, +32 ), q in [ (w>>2)*64, +64 )
    float acc[2][8][4];
    #pragma unroll
    for (int mt = 0; mt < 2; ++mt)
        #pragma unroll
        for (int nt = 0; nt < 8; ++nt)
            #pragma unroll
            for (int c = 0; c < 4; ++c) acc[mt][nt][c] = 0.0f;

    const int pbase = (w & 3) * 32;
    const int qbase = (w >> 2) * 64;

    auto mma_set = [&](int s) {
        const char* preT_s = smem + OFF_TILES + s * SET_BYTES;
        const char* hT_s   = preT_s + TILE_BYTES;
        #pragma unroll
        for (int ks = 0; ks < SC / 16; ++ks) {
            const int k0 = ks * 16;
            unsigned a[2][4];
            #pragma unroll
            for (int mt = 0; mt < 2; ++mt) {
                const int arow  = pbase + mt * 16 + (lane & 15);
                const int abyte = (k0 + ((lane >> 4) << 3)) * 2;
                const unsigned aaddr = smem_u32(
                    preT_s + arow * 128 + (((unsigned)abyte) ^ (((unsigned)arow & 7) << 4)));
                asm volatile(
                    "ldmatrix.sync.aligned.m8n8.x4.shared.b16 {%0,%1,%2,%3}, [%4];\n"
                    : "=r"(a[mt][0]), "=r"(a[mt][1]), "=r"(a[mt][2]), "=r"(a[mt][3])
                    : "r"(aaddr));
            }
            #pragma unroll
            for (int nt = 0; nt < 8; ++nt) {
                const int brow  = qbase + nt * 8 + (lane & 7);
                const int bbyte = (k0 + (((lane >> 3) & 1) << 3)) * 2;
                const unsigned baddr = smem_u32(
                    hT_s + brow * 128 + (((unsigned)bbyte) ^ (((unsigned)brow & 7) << 4)));
                unsigned b0, b1;
                asm volatile(
                    "ldmatrix.sync.aligned.m8n8.x2.shared.b16 {%0,%1}, [%2];\n"
                    : "=r"(b0), "=r"(b1) : "r"(baddr));
                #pragma unroll
                for (int mt = 0; mt < 2; ++mt) {
                    asm volatile(
                        "mma.sync.aligned.m16n8k16.row.col.f32.bf16.bf16.f32 "
                        "{%0,%1,%2,%3}, {%4,%5,%6,%7}, {%8,%9}, {%0,%1,%2,%3};\n"
                        : "+f"(acc[mt][nt][0]), "+f"(acc[mt][nt][1]),
                          "+f"(acc[mt][nt][2]), "+f"(acc[mt][nt][3])
                        : "r"(a[mt][0]), "r"(a[mt][1]), "r"(a[mt][2]), "r"(a[mt][3]),
                          "r"(b0), "r"(b1));
                }
            }
        }
    };

    // ---------------- prologue ----------------
    load_post(NBLK);          // boundary block (hcarry init + s60 tail)
    load_post(NBLK - 1);
    if (w >= 4) ldg_pre(NBLK - 1);
    asm volatile("cp.async.wait_group 0;\n" ::: "memory");
    __syncthreads();
    produce(NBLK - 1, /*init_carry=*/true);      // tiles[1]
    load_post(NBLK - 2);
    load_post(NBLK - 3);                         // in flight: {14, 13}

    // ---------------- main loop: depth-3 prefetch, one barrier/iter ----------------
    for (int kt = NBLK - 1; kt >= 0; --kt) {
        if (w >= 4 && kt >= 1) ldg_pre(kt - 1);          // early LDGs
        if (kt >= 3) load_post(kt - 3);                  // flight: {kt-1, kt-2, kt-3}
        if (kt >= 3)      asm volatile("cp.async.wait_group 2;\n" ::: "memory");
        else if (kt == 2) asm volatile("cp.async.wait_group 1;\n" ::: "memory");
        else              asm volatile("cp.async.wait_group 0;\n" ::: "memory");

        __syncthreads();
        // post(kt-1) visible; tiles[kt&1] (produced last iter) visible;
        // MMA on tiles[(kt-1)&1] finished 2 iters ago -> safe to overwrite

        if (kt >= 1) produce(kt - 1, false);             // writes tiles[(kt-1)&1]
        mma_set(kt & 1);                                 // reads  tiles[kt&1]
    }

    // ---- write per-CTA partials (deterministic parallel reduce later) ----
    {
        float* outp = g_partials + (size_t)u * NPRE * NPOST;
        #pragma unroll
        for (int mt = 0; mt < 2; ++mt) {
            #pragma unroll
            for (int nt = 0; nt < 8; ++nt) {
                const int p = pbase + mt * 16 + (lane >> 2);
                const int q = qbase + nt * 8 + 2 * (lane & 3);
                *(float2*)&outp[(size_t)p * 128 + q] =
                    make_float2(acc[mt][nt][0], acc[mt][nt][1]);
                *(float2*)&outp[(size_t)(p + 8) * 128 + q] =
                    make_float2(acc[mt][nt][2], acc[mt][nt][3]);
            }
        }
    }
    if (tid < 128) g_colsum_part[u * 128 + tid] = colsum;
}

// ==========================================================================
// Kernel 2: stage-1 partial reduce (128 arrays -> 8)  +  errq (block 256)
// grid = 257 blocks x 128 threads
// ==========================================================================
__global__ __launch_bounds__(128)
void reduce1(const void* __restrict__ dtp)
{
    if (blockIdx.x < 256) {
        const int g  = blockIdx.x >> 5;                    // 0..7
        const int c  = blockIdx.x & 31;                    // 0..31
        const int i4 = c * 128 + threadIdx.x;              // float4 index 0..4095
        float4 s = make_float4(0.f, 0.f, 0.f, 0.f);
        #pragma unroll
        for (int a = 0; a < 16; ++a) {
            const float4 v = *(const float4*)
                &g_partials[(size_t)(g * 16 + a) * (NPRE * NPOST) + 4 * i4];
            s.x += v.x; s.y += v.y; s.z += v.z; s.w += v.w;
        }
        *(float4*)&g_part2[g * (NPRE * NPOST) + 4 * i4] = s;
    } else {
        // homeostatic rate error per q (fixed order)
        const int q = threadIdx.x;                         // 0..127
        float s = 0.0f;
        #pragma unroll 8
        for (int i = 0; i < NCTA; ++i) s += g_colsum_part[i * NPOST + q];
        const float dt    = decode_dt(dtp);
        const float alpha = dt / TAU_HOM;
        const float mean  = s / (float)(BATCH * TT);
        g_errq[q] = ((1.0f - alpha) * TARGET_RATE + alpha * mean) - TARGET_RATE;
    }
}

// ==========================================================================
// Kernel 3: stage-2 reduce + homeostasis -> out
// grid = 64 x 256 (one output per thread)
// ==========================================================================
__global__ __launch_bounds__(256)
void finalize(const float* __restrict__ weights, float* __restrict__ out)
{
    const int idx = blockIdx.x * blockDim.x + threadIdx.x;   // 0..16383 (p*128+q)
    const int q = idx & 127;
    float s = 0.0f;
    #pragma unroll
    for (int g = 0; g < 8; ++g) s += g_part2[g * (NPRE * NPOST) + idx];
    const float inv = 1.0f / (float)(BATCH * TT);            // 2^-17 exact
    out[idx] = s * inv - HOM_RATE * g_errq[q] * weights[idx];
}

// ==========================================================================
extern "C" void kernel_launch(void* const* d_in, const int* in_sizes, int n_in,
                              void* d_out, int out_size)
{
    const float* pre     = (const float*)d_in[0];
    const float* post    = (const float*)d_in[1];
    const float* weights = (const float*)d_in[2];
    const void*  dtp     = (n_in > 3) ? d_in[3] : nullptr;

    cudaFuncSetAttribute(stdp_main, cudaFuncAttributeMaxDynamicSharedMemorySize, SMEM_BYTES);
    stdp_main<<<NCTA, 256, SMEM_BYTES>>>(pre, post, dtp);
    reduce1<<<257, 128>>>(dtp);
    finalize<<<(NPRE * NPOST) / 256, 256>>>(weights, (float*)d_out);
    (void)in_sizes; (void)out_size;
}

// round 17
// speedup vs baseline: 1.1150x; 1.1150x over previous
#include <cuda_runtime.h>
#include <cuda_fp16.h>
#include <cstdint>

// ---------------- problem constants ----------------
#define BATCH   16
#define TT      8192
#define NPRE    128
#define NPOST   128
#define CHUNK   1024              // timesteps per CTA (one b each)
#define SC      64                // sub-chunk (MMA K tile / pipeline block)
#define NBLK    (CHUNK / SC)      // 16 compute blocks per CTA
#define NCTA    (BATCH * TT / CHUNK)  // 128
#define LWIN    60                // filter length (taps 1..59)

#define TAU_F       20.0f
#define A_PLUS_F    0.005f
#define A_MINUS_F   0.00525f
#define TARGET_RATE 0.1f
#define HOM_RATE    0.001f
#define TAU_HOM     1000.0f
#define HSCALE      1024.0f       // power-of-2 scale for f16 h storage

// ---------------- smem layout (R2-proven) ----------------
#define POST_SLOT_BYTES (SC * 128 * 4)        // 32768, 3 slots (ring)
#define PRE_ROW_F       136                   // floats per staged pre row (bank-rotation pad)
#define PRE_SLOT_BYTES  (SC * PRE_ROW_F * 4)  // 34816, 2 slots
#define STRIDE_H        72                    // halves per row in preT/hT (conflict-free ldmatrix)
#define HT_BYTES        (128 * STRIDE_H * 2)  // 18432

#define OFF_POST 0
#define OFF_PRE  (3 * POST_SLOT_BYTES)                  // 98304
#define OFF_PRET (OFF_PRE + 2 * PRE_SLOT_BYTES)         // 167936
#define OFF_HT   (OFF_PRET + HT_BYTES)                  // 186368
#define SMEM_BYTES (OFF_HT + HT_BYTES)                  // 204800

// ---------------- scratch (static device, no allocs) ----------------
__device__ float g_partials[(size_t)NCTA * NPRE * NPOST];   // 8 MB
__device__ float g_colsum_part[NCTA * NPOST];               // 64 KB

__device__ __forceinline__ float decode_dt(const void* p) {
    if (p == nullptr) return 1.0f;
    int iv = *(const int*)p;
    if (iv >= 1 && iv <= 1000000) return (float)iv;   // int32/int64 low word
    return *(const float*)p;                          // float32 bits
}

__device__ __forceinline__ unsigned smem_u32(const void* p) {
    return (unsigned)__cvta_generic_to_shared(p);
}

// ==========================================================================
// Kernel 1: cp.async-pipelined filter + transpose + HMMA partial GEMM
// (R2-proven structure: 3-slot post ring, 2-slot fp32 pre stage, f16 MMA)
// grid = 128 CTAs (one (b, 1024-t) unit each), 256 threads
// ==========================================================================
__global__ __launch_bounds__(256, 1)
void stdp_main(const float* __restrict__ pre, const float* __restrict__ post,
               const void* __restrict__ dtp)
{
    extern __shared__ char smem[];
    char*   post_base = smem + OFF_POST;     // 3 slots of [64 t][128 q] fp32
    char*   pre_base  = smem + OFF_PRE;      // 2 slots of [64 t][136 f] fp32
    __half* preT      = (__half*)(smem + OFF_PRET);  // [128 p][72 t] f16
    __half* hT        = (__half*)(smem + OFF_HT);    // [128 q][72 t] f16

    const int tid  = threadIdx.x;
    const int lane = tid & 31;
    const int w    = tid >> 5;
    const int u    = blockIdx.x;
    const int b    = u >> 3;               // 8 units per batch
    const int t0   = (u & 7) * CHUNK;

    const float dt  = decode_dt(dtp);
    const float r   = expf(-dt / TAU_F);
    const float g0  = A_PLUS_F - A_MINUS_F;          // TAU_PLUS == TAU_MINUS
    const float c1  = r * g0;
    const float c60 = g0 * expf(-60.0f * dt / TAU_F);

    const char* postg = (const char*)(post + (size_t)b * TT * 128);
    const char* preg  = (const char*)(pre  + (size_t)b * TT * 128);

    // cp.async loader for block k: post block k (k in 0..16), pre block k (k<=15)
    auto load_block = [&](int k) {
        const int tb0 = t0 + k * SC;
        #pragma unroll 2
        for (int i = tid; i < SC * 32; i += 256) {            // 2048 x 16B
            const int rr = i >> 5, cc = i & 31;
            const int t  = tb0 + rr;
            const unsigned dst = smem_u32(post_base + (k % 3) * POST_SLOT_BYTES
                                          + rr * 512 + cc * 16);
            const char* src = postg + ((size_t)(t < TT ? t : 0) * 512 + cc * 16);
            const int ss = (t < TT) ? 16 : 0;                 // zero-fill past T
            asm volatile("cp.async.cg.shared.global [%0], [%1], 16, %2;\n"
                         :: "r"(dst), "l"(src), "r"(ss));
        }
        if (k < NBLK) {
            #pragma unroll 2
            for (int i = tid; i < SC * 32; i += 256) {
                const int rr = i >> 5, cc = i & 31;
                const int t  = tb0 + rr;                      // always < TT
                const unsigned dst = smem_u32(pre_base + (k & 1) * PRE_SLOT_BYTES
                                              + rr * (PRE_ROW_F * 4) + cc * 16);
                asm volatile("cp.async.cg.shared.global [%0], [%1], 16, 16;\n"
                             :: "r"(dst), "l"(preg + ((size_t)t * 512 + cc * 16)));
            }
        }
        asm volatile("cp.async.commit_group;\n");
    };

    // MMA accumulators: warp w -> p in [ (w&3)*32, +32 ), q in [ (w>>2)*64, +64 )
    float acc[2][8][4];
    #pragma unroll
    for (int mt = 0; mt < 2; ++mt)
        #pragma unroll
        for (int nt = 0; nt < 8; ++nt)
            #pragma unroll
            for (int c = 0; c < 4; ++c) acc[mt][nt][c] = 0.0f;

    float hcarry = 0.0f;   // filter state (tid < 128, one q each)
    float colsum = 0.0f;

    // prologue: prefetch the boundary block (16) and the first compute block (15)
    load_block(NBLK);        // block 16: only s60 tail + hcarry init
    load_block(NBLK - 1);

    for (int kt = NBLK - 1; kt >= 0; --kt) {
        if (kt > 0) load_block(kt - 1);                 // depth-1 prefetch
        if (kt > 0) asm volatile("cp.async.wait_group 1;\n");
        else        asm volatile("cp.async.wait_group 0;\n");
        __syncthreads();    // staging ready + previous MMA reads of preT/hT done

        const float* cur = (const float*)(post_base + (kt % 3) * POST_SLOT_BYTES);
        const float* nxt = (const float*)(post_base + ((kt + 1) % 3) * POST_SLOT_BYTES);

        if (tid < 128) {
            // ---------- h filter (exact backward recurrence), write hT[q][t] ----------
            const int q = tid;
            if (kt == NBLK - 1) {
                // init h[t0+1023] by direct truncated 59-tap sum over block 16
                float hh = 0.0f, wc = g0;
                #pragma unroll 4
                for (int tau = 1; tau < LWIN; ++tau) {
                    wc *= r;
                    hh += wc * nxt[(tau - 1) * 128 + q];
                }
                hcarry = hh;
            }
            #pragma unroll
            for (int g8 = SC / 8 - 1; g8 >= 0; --g8) {
                unsigned hp0 = 0, hp1 = 0, hp2 = 0, hp3 = 0, stash = 0;
                #pragma unroll
                for (int e = 7; e >= 0; --e) {
                    const int lt = g8 * 8 + e;
                    const unsigned uh = __half_as_ushort(__float2half_rn(hcarry * HSCALE));
                    if (e & 1) stash = uh << 16;
                    else {
                        const unsigned wv = stash | uh;
                        if (e == 0) hp0 = wv; else if (e == 2) hp1 = wv;
                        else if (e == 4) hp2 = wv; else hp3 = wv;
                    }
                    const float s1  = cur[lt * 128 + q];
                    const float s60 = (lt < 5) ? cur[(lt + 59) * 128 + q]
                                               : nxt[(lt - 5) * 128 + q];
                    colsum += s1;   // exact integer column count over [ts, ts+SC)
                    hcarry = fmaf(r, hcarry, fmaf(c1, s1, -c60 * s60));
                }
                uint4 v; v.x = hp0; v.y = hp1; v.z = hp2; v.w = hp3;
                *(uint4*)(hT + q * STRIDE_H + g8 * 8) = v;   // STS.128, conflict-free
            }
        } else {
            // ---------- transpose pre (from smem stage) -> preT[p][t] f16 ----------
            const int wi = w - 4;   // 0..3
            const float* ps = (const float*)(pre_base + (kt & 1) * PRE_SLOT_BYTES);
            #pragma unroll
            for (int it = 0; it < 8; ++it) {
                const int tile = wi * 8 + it;
                const int tb = tile & 7;      // t block of 8
                const int pb = tile >> 3;     // p block of 32
                const int trow = tb * 8 + (lane >> 2);
                const int pc   = pb * 32 + 2 * (lane & 3);
                unsigned regs[4];
                #pragma unroll
                for (int j = 0; j < 4; ++j) {
                    const float2 v = *(const float2*)(ps + (size_t)trow * PRE_ROW_F + pc + 8 * j);
                    __half2 h2 = __floats2half2_rn(v.x, v.y);
                    regs[j] = *(unsigned*)&h2;
                }
                const unsigned daddr = smem_u32(
                    preT + (pb * 32 + (lane >> 3) * 8 + (lane & 7)) * STRIDE_H + tb * 8);
                asm volatile(
                    "stmatrix.sync.aligned.m8n8.x4.trans.shared.b16 [%0], {%1,%2,%3,%4};\n"
                    :: "r"(daddr), "r"(regs[0]), "r"(regs[1]), "r"(regs[2]), "r"(regs[3]));
            }
        }
        __syncthreads();

        // ---------- MMA: acc[p][q] += preT^T . hT over K = SC ----------
        {
            const int pbase = (w & 3) * 32;
            const int qbase = (w >> 2) * 64;
            #pragma unroll
            for (int ks = 0; ks < SC / 16; ++ks) {
                const int k0 = ks * 16;
                unsigned a[2][4];
                #pragma unroll
                for (int mt = 0; mt < 2; ++mt) {
                    const int arow = pbase + mt * 16 + (lane & 15);
                    const int acol = k0 + ((lane >> 4) << 3);
                    const unsigned aaddr = smem_u32(preT + arow * STRIDE_H + acol);
                    asm volatile(
                        "ldmatrix.sync.aligned.m8n8.x4.shared.b16 {%0,%1,%2,%3}, [%4];\n"
                        : "=r"(a[mt][0]), "=r"(a[mt][1]), "=r"(a[mt][2]), "=r"(a[mt][3])
                        : "r"(aaddr));
                }
                #pragma unroll
                for (int nt = 0; nt < 8; ++nt) {
                    const int brow = qbase + nt * 8 + (lane & 7);
                    const int bcol = k0 + (((lane >> 3) & 1) << 3);
                    const unsigned baddr = smem_u32(hT + brow * STRIDE_H + bcol);
                    unsigned b0, b1;
                    asm volatile(
                        "ldmatrix.sync.aligned.m8n8.x2.shared.b16 {%0,%1}, [%2];\n"
                        : "=r"(b0), "=r"(b1) : "r"(baddr));
                    #pragma unroll
                    for (int mt = 0; mt < 2; ++mt) {
                        asm volatile(
                            "mma.sync.aligned.m16n8k16.row.col.f32.f16.f16.f32 "
                            "{%0,%1,%2,%3}, {%4,%5,%6,%7}, {%8,%9}, {%0,%1,%2,%3};\n"
                            : "+f"(acc[mt][nt][0]), "+f"(acc[mt][nt][1]),
                              "+f"(acc[mt][nt][2]), "+f"(acc[mt][nt][3])
                            : "r"(a[mt][0]), "r"(a[mt][1]), "r"(a[mt][2]), "r"(a[mt][3]),
                              "r"(b0), "r"(b1));
                    }
                }
            }
        }
    }

    // ---- write per-CTA partials (deterministic fixed-order reduce later) ----
    {
        const int pbase = (w & 3) * 32;
        const int qbase = (w >> 2) * 64;
        float* outp = g_partials + (size_t)u * NPRE * NPOST;
        #pragma unroll
        for (int mt = 0; mt < 2; ++mt) {
            #pragma unroll
            for (int nt = 0; nt < 8; ++nt) {
                const int p = pbase + mt * 16 + (lane >> 2);
                const int q = qbase + nt * 8 + 2 * (lane & 3);
                *(float2*)&outp[(size_t)p * 128 + q] =
                    make_float2(acc[mt][nt][0], acc[mt][nt][1]);
                *(float2*)&outp[(size_t)(p + 8) * 128 + q] =
                    make_float2(acc[mt][nt][2], acc[mt][nt][3]);
            }
        }
    }
    if (tid < 128) g_colsum_part[u * 128 + tid] = colsum;
}

// ==========================================================================
// Kernel 2 (SINGLE tail launch): fixed-order partial reduce + inline
// homeostatic error + output.   grid = 128 x 128, one output per thread.
//   - colsum loads hit L2 (64 KB array shared by all blocks)
//   - partials loads coalesced per warp (consecutive idx -> consecutive 4B)
// ==========================================================================
__global__ __launch_bounds__(128)
void finalize(const float* __restrict__ weights, float* __restrict__ out,
              const void* __restrict__ dtp)
{
    const int idx = blockIdx.x * blockDim.x + threadIdx.x;   // 0..16383 (p*128+q)
    const int q = idx & 127;

    // homeostatic rate error for this q (fixed order; exact integer sums)
    float cs = 0.0f;
    #pragma unroll 8
    for (int i = 0; i < NCTA; ++i) cs += g_colsum_part[i * NPOST + q];
    const float dt    = decode_dt(dtp);
    const float alpha = dt / TAU_HOM;
    const float mean  = cs / (float)(BATCH * TT);
    const float err   = ((1.0f - alpha) * TARGET_RATE + alpha * mean) - TARGET_RATE;

    // fixed-order reduce over the 128 per-CTA partials
    float s = 0.0f;
    #pragma unroll 8
    for (int i = 0; i < NCTA; ++i) s += g_partials[(size_t)i * (NPRE * NPOST) + idx];

    const float inv = 1.0f / (HSCALE * (float)(BATCH * TT));  // 2^-27 exact
    out[idx] = s * inv - HOM_RATE * err * weights[idx];
}

// ==========================================================================
extern "C" void kernel_launch(void* const* d_in, const int* in_sizes, int n_in,
                              void* d_out, int out_size)
{
    const float* pre     = (const float*)d_in[0];
    const float* post    = (const float*)d_in[1];
    const float* weights = (const float*)d_in[2];
    const void*  dtp     = (n_in > 3) ? d_in[3] : nullptr;

    cudaFuncSetAttribute(stdp_main, cudaFuncAttributeMaxDynamicSharedMemorySize, SMEM_BYTES);
    stdp_main<<<NCTA, 256, SMEM_BYTES>>>(pre, post, dtp);
    finalize<<<(NPRE * NPOST) / 128, 128>>>(weights, (float*)d_out, dtp);
    (void)in_sizes; (void)out_size;
}